// round 6
// baseline (speedup 1.0000x reference)
#include <cuda_runtime.h>

#define BATCH  8
#define SEQ    4096
#define DMODEL 512

// 256 threads/block: two half-blocks, each half covers one sequence position
// (128 threads x float4 = D=512). Each block processes 2 positions per
// iteration and 2 iterations (s and s+2048) => grid = 1024 CTAs = ONE wave on
// 152 SMs. Tokens for iteration 2 are prefetched during iteration 1 so the
// memory pipe never drains. Output stores use __stcs (write-once stream,
// keeps the 65MB embedding table resident in L2).
__global__ void __launch_bounds__(256)
embed_pe_kernel(const int* __restrict__ tokens,
                const float* __restrict__ table,
                float* __restrict__ out)
{
    const int t    = threadIdx.x;
    const int h    = t >> 7;        // 0/1 : which position in the pair
    const int lane = t & 127;
    const int d0   = lane << 2;     // 0,4,...,508

    int s = (blockIdx.x << 1) + h;  // 0..2047 first iteration

    // d-dependent part of PE is loop-invariant: w = 10000^(2*i/512)
    float inv_w[4];
#pragma unroll
    for (int j = 0; j < 4; ++j) {
        const float fi = (float)(d0 + j);
        inv_w[j] = exp2f(fi * (-2.0f / (float)DMODEL) * 13.287712379549449f);
    }

    // tokens for iteration 0
    int tok[BATCH];
#pragma unroll
    for (int b = 0; b < BATCH; ++b)
        tok[b] = __ldg(tokens + b * SEQ + s);

#pragma unroll
    for (int it = 0; it < 2; ++it) {
        // fire all 8 gathers for this position
        float4 e[BATCH];
#pragma unroll
        for (int b = 0; b < BATCH; ++b)
            e[b] = *reinterpret_cast<const float4*>(
                table + (size_t)tok[b] * DMODEL + d0);

        // prefetch next iteration's tokens while gathers are in flight
        int ntok[BATCH];
        if (it == 0) {
#pragma unroll
            for (int b = 0; b < BATCH; ++b)
                ntok[b] = __ldg(tokens + b * SEQ + (s + 2048));
        }

        // PE for (s, d0..d0+3) — overlaps with the loads above
        const float ps = (float)s;
        float pe[4];
#pragma unroll
        for (int j = 0; j < 4; ++j) {
            const float angle = ps * inv_w[j];
            pe[j] = ((d0 + j) & 1) ? cosf(angle) : sinf(angle);
        }

        // add + streaming stores
#pragma unroll
        for (int b = 0; b < BATCH; ++b) {
            float4 o;
            o.x = e[b].x + pe[0];
            o.y = e[b].y + pe[1];
            o.z = e[b].z + pe[2];
            o.w = e[b].w + pe[3];
            __stcs(reinterpret_cast<float4*>(
                       out + ((size_t)(b * SEQ + s)) * DMODEL + d0), o);
        }

        s += 2048;
#pragma unroll
        for (int b = 0; b < BATCH; ++b) tok[b] = ntok[b];
    }
}

extern "C" void kernel_launch(void* const* d_in, const int* in_sizes, int n_in,
                              void* d_out, int out_size)
{
    const int*   tokens = (const int*)d_in[0];   // [B, S] int32
    const float* table  = (const float*)d_in[1]; // [VOCAB, D] f32
    float*       out    = (float*)d_out;         // [B, S, D] f32
    (void)in_sizes; (void)n_in; (void)out_size;

    embed_pe_kernel<<<SEQ / 4, 256>>>(tokens, table, out);  // 1024 CTAs
}

// round 8
// speedup vs baseline: 1.0019x; 1.0019x over previous
#include <cuda_runtime.h>

#define BATCH  8
#define SEQ    4096
#define DMODEL 512

// One CTA per sequence position s (grid=4096), 128 threads x float4 = D=512.
// __launch_bounds__(128, 12): cap regs ~42 so 12 CTAs/SM stay resident (75%
// occupancy) — the R2/R3 kernels were register-capped at 50% and L2-hit
// latency-bound. Batch rows processed in two groups of 4 to keep only 4
// float4s in flight (fits the reg budget); group-1 gathers overlap the PE
// sin/cos, group-2 gathers overlap group-1 stores.
__global__ void __launch_bounds__(128, 12)
embed_pe_kernel(const int* __restrict__ tokens,
                const float* __restrict__ table,
                float* __restrict__ out)
{
    const int s  = blockIdx.x;      // 0..SEQ-1
    const int t  = threadIdx.x;     // 0..127
    const int d0 = t << 2;          // 0,4,...,508

    // 1) tokens group 1 + fire their gathers
    int tok[BATCH];
#pragma unroll
    for (int b = 0; b < 4; ++b)
        tok[b] = __ldg(tokens + b * SEQ + s);

    float4 e[4];
#pragma unroll
    for (int b = 0; b < 4; ++b)
        e[b] = *reinterpret_cast<const float4*>(
            table + (size_t)tok[b] * DMODEL + d0);

    // 2) tokens group 2 (in flight alongside)
#pragma unroll
    for (int b = 4; b < BATCH; ++b)
        tok[b] = __ldg(tokens + b * SEQ + s);

    // 3) PE for (s, d0..d0+3) — overlaps with in-flight gathers
    const float ps = (float)s;
    float pe[4];
#pragma unroll
    for (int j = 0; j < 4; ++j) {
        const float fi = (float)(d0 + j);
        // 1/10000^(2*i/D) = exp2(-(2*i/D)*log2(10000))
        const float inv_w = exp2f(fi * (-2.0f / (float)DMODEL) * 13.287712379549449f);
        const float angle = ps * inv_w;
        pe[j] = ((d0 + j) & 1) ? cosf(angle) : sinf(angle);
    }

    // 4) group-1 stores (streaming: keep table L2-resident)
#pragma unroll
    for (int b = 0; b < 4; ++b) {
        float4 o;
        o.x = e[b].x + pe[0];
        o.y = e[b].y + pe[1];
        o.z = e[b].z + pe[2];
        o.w = e[b].w + pe[3];
        __stcs(reinterpret_cast<float4*>(
                   out + ((size_t)(b * SEQ + s)) * DMODEL + d0), o);
    }

    // 5) group-2 gathers (register reuse) + stores
#pragma unroll
    for (int b = 0; b < 4; ++b)
        e[b] = *reinterpret_cast<const float4*>(
            table + (size_t)tok[4 + b] * DMODEL + d0);

#pragma unroll
    for (int b = 0; b < 4; ++b) {
        float4 o;
        o.x = e[b].x + pe[0];
        o.y = e[b].y + pe[1];
        o.z = e[b].z + pe[2];
        o.w = e[b].w + pe[3];
        __stcs(reinterpret_cast<float4*>(
                   out + ((size_t)((4 + b) * SEQ + s)) * DMODEL + d0), o);
    }
}

extern "C" void kernel_launch(void* const* d_in, const int* in_sizes, int n_in,
                              void* d_out, int out_size)
{
    const int*   tokens = (const int*)d_in[0];   // [B, S] int32
    const float* table  = (const float*)d_in[1]; // [VOCAB, D] f32
    float*       out    = (float*)d_out;         // [B, S, D] f32
    (void)in_sizes; (void)n_in; (void)out_size;

    embed_pe_kernel<<<SEQ, 128>>>(tokens, table, out);
}